// round 10
// baseline (speedup 1.0000x reference)
#include <cuda_runtime.h>
#include <math.h>

#define BATCH 8
#define DOUT  16

// ---------------------------------------------------------------------------
// Scratch (device globals -- no allocation allowed)
// ---------------------------------------------------------------------------
__device__ float g_pred[(size_t)BATCH * 596 * 100 * DOUT];   // max: level 2, 30.5 MB
// S regions (S | S2) per level, disjoint:
//   L0: [0,2048)   L1: [2048,7168)   L2: [7168,32768)
// INVARIANT: g_S is all-zero at kernel_launch entry (BSS at init; each route
// kernel's tail block re-zeros its level's region after the final squash).
__device__ float g_S[32768];
__device__ unsigned g_ctr[4];   // zero-initialized; each use self-resets

#define SOFF0 0
#define SOFF1 2048
#define SOFF2 7168

// ---------------------------------------------------------------------------
// squash of one 16-dim capsule: out = (sq/(1+sq)) * s / sqrt(sq+eps), s = in*scale
// ---------------------------------------------------------------------------
__device__ __forceinline__ void squash16(const float* __restrict__ s, float scale,
                                         float* __restrict__ out)
{
    float4 a[4];
    float sq = 0.f;
#pragma unroll
    for (int j = 0; j < 4; j++) {
        float4 t = __ldcg(reinterpret_cast<const float4*>(s) + j);
        t.x *= scale; t.y *= scale; t.z *= scale; t.w *= scale;
        sq += t.x*t.x + t.y*t.y + t.z*t.z + t.w*t.w;
        a[j] = t;
    }
    float f = sq / ((1.f + sq) * sqrtf(sq + 1e-7f));
#pragma unroll
    for (int j = 0; j < 4; j++) {
        a[j].x *= f; a[j].y *= f; a[j].z *= f; a[j].w *= f;
        reinterpret_cast<float4*>(out)[j] = a[j];
    }
}

// ---------------------------------------------------------------------------
// pred[b,i,c,d] = sum_k W[i,c,d,k] * Xlvl[b,i,k]
// also accumulates S[b,c,d] += sum_i pred  (register acc + 1 atomic/thread/b)
// ---------------------------------------------------------------------------
template<int N, int C, int K, int IPAR, int ILOOP, int CTILE>
__global__ __launch_bounds__(IPAR * CTILE * DOUT)
void pred_kernel(const float* __restrict__ X,
                 const float* __restrict__ W,
                 const float* __restrict__ Vprev,
                 int skip, int cprev, int soff)
{
    constexpr int ICHUNK = IPAR * ILOOP;
    constexpr int TPB    = IPAR * CTILE * DOUT;
    constexpr int K4     = K / 4;
    __shared__ float Xs[ICHUNK][BATCH][K];

    const int tid = threadIdx.x;
    const int i0  = blockIdx.x * ICHUNK;

    for (int idx = tid; idx < ICHUNK * BATCH * K; idx += TPB) {
        int il = idx / (BATCH * K);
        int r  = idx % (BATCH * K);
        int b  = r / K, k = r % K;
        int gi = i0 + il;
        float v;
        if (gi < skip) v = X[b * 9216 + gi * K + k];
        else           v = Vprev[(b * cprev + (gi - skip)) * DOUT + k];
        Xs[il][b][k] = v;
    }
    __syncthreads();

    const int isub  = tid / (CTILE * DOUT);
    const int rem   = tid % (CTILE * DOUT);
    const int c     = blockIdx.y * CTILE + rem / DOUT;
    const int d     = rem % DOUT;
    const int ibase = isub * ILOOP;

    float acc[BATCH];
#pragma unroll
    for (int b = 0; b < BATCH; b++) acc[b] = 0.f;

    // prefetch first W tile
    float4 wc[K4];
    {
        const float* wp = W + ((size_t)((i0 + ibase) * C + c) * DOUT + d) * K;
#pragma unroll
        for (int k4 = 0; k4 < K4; k4++)
            wc[k4] = __ldcg(reinterpret_cast<const float4*>(wp) + k4);
    }

#pragma unroll
    for (int il2 = 0; il2 < ILOOP; ++il2) {
        float4 wn[K4];
        if (il2 + 1 < ILOOP) {
            const float* wp =
                W + ((size_t)((i0 + ibase + il2 + 1) * C + c) * DOUT + d) * K;
#pragma unroll
            for (int k4 = 0; k4 < K4; k4++)
                wn[k4] = __ldcg(reinterpret_cast<const float4*>(wp) + k4);
        }
        const int iloc = ibase + il2;
        const int i    = i0 + iloc;
        float w[K];
#pragma unroll
        for (int k4 = 0; k4 < K4; k4++) {
            w[4*k4+0] = wc[k4].x; w[4*k4+1] = wc[k4].y;
            w[4*k4+2] = wc[k4].z; w[4*k4+3] = wc[k4].w;
        }
#pragma unroll
        for (int b = 0; b < BATCH; b++) {
            float p = 0.f;
#pragma unroll
            for (int k = 0; k < K; k++) p += w[k] * Xs[iloc][b][k];
            acc[b] += p;
            __stcg(&g_pred[(((size_t)b * N + i) * C + c) * DOUT + d], p);
        }
#pragma unroll
        for (int k4 = 0; k4 < K4; k4++) wc[k4] = wn[k4];
    }
#pragma unroll
    for (int b = 0; b < BATCH; b++)
        atomicAdd(&g_S[soff + (b * C + c) * DOUT + d], acc[b]);
}

// ---------------------------------------------------------------------------
// route level 0: C=8, CD=128, N=1152.  grid (76, 8), block 256 (608 warps/b).
// warp-per-i-stripe; lane holds 4 (c,d) elems; no inner syncs; no-max softmax
// (|logit| <= ||pred||*||v|| bounded, exp cannot overflow).
// Butterfly over xor {4,8,16} spans 8 lanes = one lane per capsule group,
// so the reduced sum is exactly sum_c e_c.
// ---------------------------------------------------------------------------
__global__ __launch_bounds__(256) void route0_kernel(float* __restrict__ v0)
{
    __shared__ float vsh[128];
    __shared__ unsigned s_done;
    const int tid = threadIdx.x, lane = tid & 31, warp = tid >> 5;
    const int b = blockIdx.y;

    if (tid < 8)
        squash16(&g_S[SOFF0 + b * 128 + tid * 16], 0.125f, &vsh[tid * 16]);
    __syncthreads();

    const float4 v4 = *reinterpret_cast<const float4*>(&vsh[lane * 4]);
    float ax = 0.f, ay = 0.f, az = 0.f, aw = 0.f;
    const int wg = blockIdx.x * 8 + warp;           // 0..607 per b

    for (int i = wg; i < 1152; i += 608) {
        float4 p = __ldcg(reinterpret_cast<const float4*>(
            g_pred + ((size_t)(b * 1152 + i)) * 128 + lane * 4));
        float lg = p.x*v4.x + p.y*v4.y + p.z*v4.z + p.w*v4.w;
        lg += __shfl_xor_sync(~0u, lg, 1);
        lg += __shfl_xor_sync(~0u, lg, 2);          // logit for c = lane/4
        float e = __expf(lg);
        float s = e;
        s += __shfl_xor_sync(~0u, s, 4);
        s += __shfl_xor_sync(~0u, s, 8);
        s += __shfl_xor_sync(~0u, s, 16);           // = sum_c e_c (once each)
        float w = e / s;
        ax += w * p.x; ay += w * p.y; az += w * p.z; aw += w * p.w;
    }
    float* S2 = &g_S[SOFF0 + 1024 + b * 128 + lane * 4];
    atomicAdd(S2 + 0, ax); atomicAdd(S2 + 1, ay);
    atomicAdd(S2 + 2, az); atomicAdd(S2 + 3, aw);

    __threadfence();
    __syncthreads();
    if (tid == 0) s_done = atomicAdd(&g_ctr[0], 1u);
    __syncthreads();
    if (s_done == 607u) {                            // last of 608 blocks
        __threadfence();
        if (tid < 64)
            squash16(&g_S[SOFF0 + 1024 + tid * 16], 1.f, v0 + tid * 16);
        __syncthreads();
        for (int e = tid; e < 2048; e += 256) g_S[SOFF0 + e] = 0.f;
        if (tid == 0) g_ctr[0] = 0u;
    }
}

// ---------------------------------------------------------------------------
// route level 1: C=20, CD=320, N=584.  grid (80, 8), block 256 (640 warps/b).
// lane layout: element 32*cc + lane  (c = 2*cc + lane/16, d = lane%16)
// ---------------------------------------------------------------------------
__global__ __launch_bounds__(256) void route1_kernel(float* __restrict__ v1)
{
    __shared__ float vsh[320];
    __shared__ unsigned s_done;
    const int tid = threadIdx.x, lane = tid & 31, warp = tid >> 5;
    const int b = blockIdx.y;

    if (tid < 20)
        squash16(&g_S[SOFF1 + b * 320 + tid * 16], 1.f / 20.f, &vsh[tid * 16]);
    __syncthreads();

    float v[10], acc[10];
#pragma unroll
    for (int cc = 0; cc < 10; cc++) { v[cc] = vsh[32 * cc + lane]; acc[cc] = 0.f; }

    const int wg = blockIdx.x * 8 + warp;           // 0..639 per b
    for (int i = wg; i < 584; i += 640) {
        const float* pb = g_pred + ((size_t)(b * 584 + i)) * 320;
        float p[10], lg[10];
#pragma unroll
        for (int cc = 0; cc < 10; cc++) {
            p[cc] = __ldcg(pb + 32 * cc + lane);
            float t = p[cc] * v[cc];
            t += __shfl_xor_sync(~0u, t, 1);
            t += __shfl_xor_sync(~0u, t, 2);
            t += __shfl_xor_sync(~0u, t, 4);
            t += __shfl_xor_sync(~0u, t, 8);
            lg[cc] = t;
        }
        float tot = 0.f;
#pragma unroll
        for (int cc = 0; cc < 10; cc++) { lg[cc] = __expf(lg[cc]); tot += lg[cc]; }
        tot += __shfl_xor_sync(~0u, tot, 16);
        float inv = 1.f / tot;
#pragma unroll
        for (int cc = 0; cc < 10; cc++) acc[cc] += lg[cc] * inv * p[cc];
    }
#pragma unroll
    for (int cc = 0; cc < 10; cc++)
        atomicAdd(&g_S[SOFF1 + 2560 + b * 320 + 32 * cc + lane], acc[cc]);

    __threadfence();
    __syncthreads();
    if (tid == 0) s_done = atomicAdd(&g_ctr[1], 1u);
    __syncthreads();
    if (s_done == 639u) {                            // last of 640 blocks
        __threadfence();
        if (tid < 160)
            squash16(&g_S[SOFF1 + 2560 + tid * 16], 1.f, v1 + tid * 16);
        __syncthreads();
        for (int e = tid; e < 5120; e += 256) g_S[SOFF1 + e] = 0.f;
        if (tid == 0) g_ctr[1] = 0u;
    }
}

// ---------------------------------------------------------------------------
// route level 2: C=100, CD=1600, N=596.  grid (114, 8), block 128 (4 warps).
// 456 warps/b; pred row kept in registers; per-warp smem accumulator; logits
// staged via per-warp smem so exps are ~3/lane instead of 50/lane.
// ---------------------------------------------------------------------------
__global__ __launch_bounds__(128) void route2_kernel(float* __restrict__ v2)
{
    __shared__ float vsh[1600];
    __shared__ float sacc[4][1600];
    __shared__ float slog[4][100];
    __shared__ unsigned s_done;
    const int tid = threadIdx.x, lane = tid & 31, warp = tid >> 5;
    const int b = blockIdx.y;
    const int half = lane >> 4;

    if (tid < 100)
        squash16(&g_S[SOFF2 + b * 1600 + tid * 16], 0.01f, &vsh[tid * 16]);
    for (int e = tid; e < 4 * 1600; e += 128) (&sacc[0][0])[e] = 0.f;
    __syncthreads();

    float* sa = sacc[warp];
    float* sl = slog[warp];
    const int wg = blockIdx.x * 4 + warp;           // 0..455 per b

    for (int i = wg; i < 596; i += 456) {
        const float* pb = g_pred + ((size_t)(b * 596 + i)) * 1600;
        float p[50];
#pragma unroll
        for (int cc = 0; cc < 50; cc++) {
            p[cc] = __ldcg(pb + 32 * cc + lane);
            float t = p[cc] * vsh[32 * cc + lane];
            t += __shfl_xor_sync(~0u, t, 1);
            t += __shfl_xor_sync(~0u, t, 2);
            t += __shfl_xor_sync(~0u, t, 4);
            t += __shfl_xor_sync(~0u, t, 8);
            if ((lane & 15) == 0) sl[2 * cc + half] = t;   // logit c = 2cc+half
        }
        __syncwarp();
        // distributed softmax (no max; logits bounded): lane handles
        // c = lane, lane+32, lane+64 (,lane+96 for lane<4)
        float e0 = __expf(sl[lane]);
        float e1 = __expf(sl[lane + 32]);
        float e2 = __expf(sl[lane + 64]);
        float e3 = (lane < 4) ? __expf(sl[lane + 96]) : 0.f;
        float tot = e0 + e1 + e2 + e3;
#pragma unroll
        for (int o = 16; o; o >>= 1) tot += __shfl_xor_sync(~0u, tot, o);
        sl[lane] = e0; sl[lane + 32] = e1; sl[lane + 64] = e2;
        if (lane < 4) sl[lane + 96] = e3;
        __syncwarp();
        float inv = 1.f / tot;
#pragma unroll
        for (int cc = 0; cc < 50; cc++) {
            float w = sl[2 * cc + half] * inv;       // broadcast LDS
            sa[32 * cc + lane] += w * p[cc];
        }
    }
    __syncthreads();
    for (int e = tid; e < 1600; e += 128) {
        float s = sacc[0][e] + sacc[1][e] + sacc[2][e] + sacc[3][e];
        atomicAdd(&g_S[SOFF2 + 12800 + b * 1600 + e], s);
    }

    __threadfence();
    __syncthreads();
    if (tid == 0) s_done = atomicAdd(&g_ctr[2], 1u);
    __syncthreads();
    if (s_done == 911u) {                            // last of 912 blocks
        __threadfence();
        for (int cap = tid; cap < 800; cap += 128)
            squash16(&g_S[SOFF2 + 12800 + cap * 16], 1.f, v2 + cap * 16);
        __syncthreads();
        for (int e = tid; e < 25600; e += 128) g_S[SOFF2 + e] = 0.f;
        if (tid == 0) g_ctr[2] = 0u;
    }
}

// ---------------------------------------------------------------------------
extern "C" void kernel_launch(void* const* d_in, const int* in_sizes, int n_in,
                              void* d_out, int out_size)
{
    const float* X  = (const float*)d_in[0];   // [8,1152,8]
    const float* W0 = (const float*)d_in[1];   // [1152,8,16,8]
    const float* W1 = (const float*)d_in[2];   // [584,20,16,16]
    const float* W2 = (const float*)d_in[3];   // [596,100,16,16]
    float* out = (float*)d_out;
    float* v0 = out;                 // [8][8][16]
    float* v1 = out + 1024;          // [8][20][16]
    float* v2 = out + 3584;          // [8][100][16]

    // ---- level 0 ----  (pred: 288 blocks x 512 thr = 31 warps/SM)
    pred_kernel<1152, 8, 8, 4, 1, 8><<<dim3(288, 1), 512>>>(X, W0, X, 1152, 1, SOFF0);
    route0_kernel<<<dim3(76, 8), 256>>>(v0);

    // ---- level 1 ----  (pred: 292 blocks x 640 thr = 39 warps/SM)
    pred_kernel<584, 20, 16, 2, 1, 20><<<dim3(292, 1), 640>>>(X, W1, v0, 576, 8, SOFF1);
    route1_kernel<<<dim3(80, 8), 256>>>(v1);

    // ---- level 2 ----  (pred: 596 blocks x 400 thr = 50 warps/SM, prefetch)
    pred_kernel<596, 100, 16, 1, 4, 25><<<dim3(149, 4), 400>>>(X, W2, v1, 576, 20, SOFF2);
    route2_kernel<<<dim3(114, 8), 128>>>(v2);
}

// round 11
// speedup vs baseline: 1.1761x; 1.1761x over previous
#include <cuda_runtime.h>
#include <math.h>

#define BATCH 8
#define DOUT  16

// ---------------------------------------------------------------------------
// Scratch (device globals -- no allocation allowed)
// ---------------------------------------------------------------------------
__device__ float g_pred[(size_t)BATCH * 596 * 100 * DOUT];   // max: level 2, 30.5 MB
// S regions (S | S2) per level, disjoint:
//   L0: [0,2048)   L1: [2048,7168)   L2: [7168,32768)
// INVARIANT: g_S is all-zero at kernel_launch entry (BSS at init; each route
// kernel's tail block re-zeros its level's region after the final squash).
__device__ float g_S[32768];
__device__ unsigned g_ctr[4];   // zero-initialized; each use self-resets

#define SOFF0 0
#define SOFF1 2048
#define SOFF2 7168

// ---------------------------------------------------------------------------
// squash: v = (sq/(1+sq)) * s / sqrt(sq+eps), s = in*scale.
// float4-out variant (16B-aligned dst) and scalar-out variant (padded smem rows).
// ---------------------------------------------------------------------------
__device__ __forceinline__ void squash16(const float* __restrict__ s, float scale,
                                         float* __restrict__ out)
{
    float4 a[4];
    float sq = 0.f;
#pragma unroll
    for (int j = 0; j < 4; j++) {
        float4 t = __ldcg(reinterpret_cast<const float4*>(s) + j);
        t.x *= scale; t.y *= scale; t.z *= scale; t.w *= scale;
        sq += t.x*t.x + t.y*t.y + t.z*t.z + t.w*t.w;
        a[j] = t;
    }
    float f = sq / ((1.f + sq) * sqrtf(sq + 1e-7f));
#pragma unroll
    for (int j = 0; j < 4; j++) {
        a[j].x *= f; a[j].y *= f; a[j].z *= f; a[j].w *= f;
        reinterpret_cast<float4*>(out)[j] = a[j];
    }
}

__device__ __forceinline__ void squash16s(const float* __restrict__ s, float scale,
                                          float* __restrict__ out)   // scalar stores
{
    float a[16];
    float sq = 0.f;
#pragma unroll
    for (int j = 0; j < 4; j++) {
        float4 t = __ldcg(reinterpret_cast<const float4*>(s) + j);
        t.x *= scale; t.y *= scale; t.z *= scale; t.w *= scale;
        sq += t.x*t.x + t.y*t.y + t.z*t.z + t.w*t.w;
        a[4*j+0] = t.x; a[4*j+1] = t.y; a[4*j+2] = t.z; a[4*j+3] = t.w;
    }
    float f = sq / ((1.f + sq) * sqrtf(sq + 1e-7f));
#pragma unroll
    for (int j = 0; j < 16; j++) out[j] = a[j] * f;
}

// ---------------------------------------------------------------------------
// pred[b,i,c,d] = sum_k W[i,c,d,k] * Xlvl[b,i,k]
// also accumulates S[b,c,d] += sum_i pred  (register acc + 1 atomic/thread/b)
// ---------------------------------------------------------------------------
template<int N, int C, int K, int IPAR, int ILOOP, int CTILE>
__global__ __launch_bounds__(IPAR * CTILE * DOUT)
void pred_kernel(const float* __restrict__ X,
                 const float* __restrict__ W,
                 const float* __restrict__ Vprev,
                 int skip, int cprev, int soff)
{
    constexpr int ICHUNK = IPAR * ILOOP;
    constexpr int TPB    = IPAR * CTILE * DOUT;
    constexpr int K4     = K / 4;
    __shared__ float Xs[ICHUNK][BATCH][K];

    const int tid = threadIdx.x;
    const int i0  = blockIdx.x * ICHUNK;

    for (int idx = tid; idx < ICHUNK * BATCH * K; idx += TPB) {
        int il = idx / (BATCH * K);
        int r  = idx % (BATCH * K);
        int b  = r / K, k = r % K;
        int gi = i0 + il;
        float v;
        if (gi < skip) v = X[b * 9216 + gi * K + k];
        else           v = Vprev[(b * cprev + (gi - skip)) * DOUT + k];
        Xs[il][b][k] = v;
    }
    __syncthreads();

    const int isub  = tid / (CTILE * DOUT);
    const int rem   = tid % (CTILE * DOUT);
    const int c     = blockIdx.y * CTILE + rem / DOUT;
    const int d     = rem % DOUT;
    const int ibase = isub * ILOOP;

    float acc[BATCH];
#pragma unroll
    for (int b = 0; b < BATCH; b++) acc[b] = 0.f;

    float4 wc[K4];
    {
        const float* wp = W + ((size_t)((i0 + ibase) * C + c) * DOUT + d) * K;
#pragma unroll
        for (int k4 = 0; k4 < K4; k4++)
            wc[k4] = __ldcg(reinterpret_cast<const float4*>(wp) + k4);
    }

#pragma unroll
    for (int il2 = 0; il2 < ILOOP; ++il2) {
        float4 wn[K4];
        if (il2 + 1 < ILOOP) {
            const float* wp =
                W + ((size_t)((i0 + ibase + il2 + 1) * C + c) * DOUT + d) * K;
#pragma unroll
            for (int k4 = 0; k4 < K4; k4++)
                wn[k4] = __ldcg(reinterpret_cast<const float4*>(wp) + k4);
        }
        const int iloc = ibase + il2;
        const int i    = i0 + iloc;
        float w[K];
#pragma unroll
        for (int k4 = 0; k4 < K4; k4++) {
            w[4*k4+0] = wc[k4].x; w[4*k4+1] = wc[k4].y;
            w[4*k4+2] = wc[k4].z; w[4*k4+3] = wc[k4].w;
        }
#pragma unroll
        for (int b = 0; b < BATCH; b++) {
            float p = 0.f;
#pragma unroll
            for (int k = 0; k < K; k++) p += w[k] * Xs[iloc][b][k];
            acc[b] += p;
            __stcg(&g_pred[(((size_t)b * N + i) * C + c) * DOUT + d], p);
        }
#pragma unroll
        for (int k4 = 0; k4 < K4; k4++) wc[k4] = wn[k4];
    }
#pragma unroll
    for (int b = 0; b < BATCH; b++)
        atomicAdd(&g_S[soff + (b * C + c) * DOUT + d], acc[b]);
}

// ---------------------------------------------------------------------------
// route level 0: C=8, CD=128, N=1152.  grid (19, 8), block 256 (152 warps/b).
// lane holds 4 (c,d) elems; unroll-2 interleaved i-pairs to overlap the
// shfl/exp chains; no-max softmax (logits bounded).
// ---------------------------------------------------------------------------
__global__ __launch_bounds__(256) void route0_kernel(float* __restrict__ v0)
{
    __shared__ float vsh[128];
    __shared__ unsigned s_done;
    const int tid = threadIdx.x, lane = tid & 31, warp = tid >> 5;
    const int b = blockIdx.y;

    if (tid < 8)
        squash16(&g_S[SOFF0 + b * 128 + tid * 16], 0.125f, &vsh[tid * 16]);
    __syncthreads();

    const float4 v4 = *reinterpret_cast<const float4*>(&vsh[lane * 4]);
    float ax = 0.f, ay = 0.f, az = 0.f, aw = 0.f;
    const int wg = blockIdx.x * 8 + warp;           // 0..151 per b
    const float* base = g_pred + (size_t)b * 1152 * 128;

    int i = wg;
    for (; i + 152 < 1152; i += 304) {
        float4 pA = __ldcg(reinterpret_cast<const float4*>(base + (size_t)i * 128 + lane * 4));
        float4 pB = __ldcg(reinterpret_cast<const float4*>(base + (size_t)(i + 152) * 128 + lane * 4));
        float lgA = pA.x*v4.x + pA.y*v4.y + pA.z*v4.z + pA.w*v4.w;
        float lgB = pB.x*v4.x + pB.y*v4.y + pB.z*v4.z + pB.w*v4.w;
        lgA += __shfl_xor_sync(~0u, lgA, 1);  lgB += __shfl_xor_sync(~0u, lgB, 1);
        lgA += __shfl_xor_sync(~0u, lgA, 2);  lgB += __shfl_xor_sync(~0u, lgB, 2);
        float eA = __expf(lgA), eB = __expf(lgB);
        float sA = eA, sB = eB;
        sA += __shfl_xor_sync(~0u, sA, 4);   sB += __shfl_xor_sync(~0u, sB, 4);
        sA += __shfl_xor_sync(~0u, sA, 8);   sB += __shfl_xor_sync(~0u, sB, 8);
        sA += __shfl_xor_sync(~0u, sA, 16);  sB += __shfl_xor_sync(~0u, sB, 16);
        float wA = eA / sA, wB = eB / sB;
        ax += wA * pA.x + wB * pB.x;  ay += wA * pA.y + wB * pB.y;
        az += wA * pA.z + wB * pB.z;  aw += wA * pA.w + wB * pB.w;
    }
    if (i < 1152) {
        float4 p = __ldcg(reinterpret_cast<const float4*>(base + (size_t)i * 128 + lane * 4));
        float lg = p.x*v4.x + p.y*v4.y + p.z*v4.z + p.w*v4.w;
        lg += __shfl_xor_sync(~0u, lg, 1);
        lg += __shfl_xor_sync(~0u, lg, 2);
        float e = __expf(lg);
        float s = e;
        s += __shfl_xor_sync(~0u, s, 4);
        s += __shfl_xor_sync(~0u, s, 8);
        s += __shfl_xor_sync(~0u, s, 16);
        float w = e / s;
        ax += w * p.x; ay += w * p.y; az += w * p.z; aw += w * p.w;
    }
    float* S2 = &g_S[SOFF0 + 1024 + b * 128 + lane * 4];
    atomicAdd(S2 + 0, ax); atomicAdd(S2 + 1, ay);
    atomicAdd(S2 + 2, az); atomicAdd(S2 + 3, aw);

    __threadfence();
    __syncthreads();
    if (tid == 0) s_done = atomicAdd(&g_ctr[0], 1u);
    __syncthreads();
    if (s_done == 151u) {                            // last of 152 blocks
        __threadfence();
        if (tid < 64)
            squash16(&g_S[SOFF0 + 1024 + tid * 16], 1.f, v0 + tid * 16);
        __syncthreads();
        for (int e = tid; e < 2048; e += 256) g_S[SOFF0 + e] = 0.f;
        if (tid == 0) g_ctr[0] = 0u;
    }
}

// ---------------------------------------------------------------------------
// route level 1: C=20, N=584.  grid (20, 8), block 256 (160 warps/b).
// LANE-OWNS-CAPSULE: lane<20 owns c=lane; pred row (16 floats) loaded as
// 4x float4; logit is a LOCAL dot (v in registers); one 5-shfl butterfly for
// the softmax denominator; acc in 16 registers. 5 shfls/i vs 41 before.
// ---------------------------------------------------------------------------
__global__ __launch_bounds__(256) void route1_kernel(float* __restrict__ v1)
{
    __shared__ float vsh[20 * 17];
    __shared__ unsigned s_done;
    const int tid = threadIdx.x, lane = tid & 31, warp = tid >> 5;
    const int b = blockIdx.y;

    if (tid < 20)
        squash16s(&g_S[SOFF1 + b * 320 + tid * 16], 0.05f, &vsh[tid * 17]);
    __syncthreads();

    const bool act = lane < 20;
    const int  c   = act ? lane : 0;
    float vr[16], acc[16];
#pragma unroll
    for (int d = 0; d < 16; d++) { vr[d] = vsh[c * 17 + d]; acc[d] = 0.f; }

    const float* base = g_pred + (size_t)b * 584 * 320 + c * 16;
    const int wg = blockIdx.x * 8 + warp;           // 0..159 per b

    int i = wg;
    for (; i + 160 < 584; i += 320) {
        const float4* rA = reinterpret_cast<const float4*>(base + (size_t)i * 320);
        const float4* rB = reinterpret_cast<const float4*>(base + (size_t)(i + 160) * 320);
        float4 a0 = __ldcg(rA + 0), a1 = __ldcg(rA + 1), a2 = __ldcg(rA + 2), a3 = __ldcg(rA + 3);
        float4 b0 = __ldcg(rB + 0), b1 = __ldcg(rB + 1), b2 = __ldcg(rB + 2), b3 = __ldcg(rB + 3);
        float pA[16] = {a0.x,a0.y,a0.z,a0.w, a1.x,a1.y,a1.z,a1.w,
                        a2.x,a2.y,a2.z,a2.w, a3.x,a3.y,a3.z,a3.w};
        float pB[16] = {b0.x,b0.y,b0.z,b0.w, b1.x,b1.y,b1.z,b1.w,
                        b2.x,b2.y,b2.z,b2.w, b3.x,b3.y,b3.z,b3.w};
        float lgA = 0.f, lgB = 0.f;
#pragma unroll
        for (int d = 0; d < 16; d++) { lgA += pA[d] * vr[d]; lgB += pB[d] * vr[d]; }
        float eA = act ? __expf(lgA) : 0.f;
        float eB = act ? __expf(lgB) : 0.f;
        float tA = eA, tB = eB;
#pragma unroll
        for (int o = 16; o; o >>= 1) {
            tA += __shfl_xor_sync(~0u, tA, o);
            tB += __shfl_xor_sync(~0u, tB, o);
        }
        float wA = eA / tA, wB = eB / tB;
#pragma unroll
        for (int d = 0; d < 16; d++) acc[d] += wA * pA[d] + wB * pB[d];
    }
    if (i < 584) {
        const float4* rA = reinterpret_cast<const float4*>(base + (size_t)i * 320);
        float4 a0 = __ldcg(rA + 0), a1 = __ldcg(rA + 1), a2 = __ldcg(rA + 2), a3 = __ldcg(rA + 3);
        float pA[16] = {a0.x,a0.y,a0.z,a0.w, a1.x,a1.y,a1.z,a1.w,
                        a2.x,a2.y,a2.z,a2.w, a3.x,a3.y,a3.z,a3.w};
        float lgA = 0.f;
#pragma unroll
        for (int d = 0; d < 16; d++) lgA += pA[d] * vr[d];
        float eA = act ? __expf(lgA) : 0.f;
        float tA = eA;
#pragma unroll
        for (int o = 16; o; o >>= 1) tA += __shfl_xor_sync(~0u, tA, o);
        float wA = eA / tA;
#pragma unroll
        for (int d = 0; d < 16; d++) acc[d] += wA * pA[d];
    }
    if (act) {
        float* S2 = &g_S[SOFF1 + 2560 + b * 320 + c * 16];
#pragma unroll
        for (int d = 0; d < 16; d++) atomicAdd(S2 + d, acc[d]);
    }

    __threadfence();
    __syncthreads();
    if (tid == 0) s_done = atomicAdd(&g_ctr[1], 1u);
    __syncthreads();
    if (s_done == 159u) {                            // last of 160 blocks
        __threadfence();
        if (tid < 160)
            squash16(&g_S[SOFF1 + 2560 + tid * 16], 1.f, v1 + tid * 16);
        __syncthreads();
        for (int e = tid; e < 5120; e += 256) g_S[SOFF1 + e] = 0.f;
        if (tid == 0) g_ctr[1] = 0u;
    }
}

// ---------------------------------------------------------------------------
// route level 2: C=100, N=596.  grid (38, 8), block 128 (152 warps/b).
// LANE-OWNS-CAPSULE: lane owns c = lane, lane+32, lane+64 (+96 for lane<4).
// Local dots against pad-17 smem v (conflict-free), 5 shfls/i total,
// per-warp pad-17 smem accumulators (race-free: one lane per row).
// ---------------------------------------------------------------------------
__global__ __launch_bounds__(128) void route2_kernel(float* __restrict__ v2)
{
    __shared__ float vsh[100 * 17];
    __shared__ float sacc[4][100 * 17];
    __shared__ unsigned s_done;
    const int tid = threadIdx.x, lane = tid & 31, warp = tid >> 5;
    const int b = blockIdx.y;
    const bool has4 = lane < 4;

    if (tid < 100)
        squash16s(&g_S[SOFF2 + b * 1600 + tid * 16], 0.01f, &vsh[tid * 17]);
    for (int e = tid; e < 4 * 1700; e += 128) (&sacc[0][0])[e] = 0.f;
    __syncthreads();

    float* sa = sacc[warp];
    const int wg = blockIdx.x * 4 + warp;           // 0..151 per b
    const float* pb_base = g_pred + (size_t)b * 596 * 1600;

    for (int i = wg; i < 596; i += 152) {
        const float* pb = pb_base + (size_t)i * 1600;
        float p[4][16];
#pragma unroll
        for (int g = 0; g < 3; g++) {
            const float4* r = reinterpret_cast<const float4*>(pb + (lane + 32 * g) * 16);
            float4 q0 = __ldcg(r + 0), q1 = __ldcg(r + 1), q2 = __ldcg(r + 2), q3 = __ldcg(r + 3);
            p[g][0]=q0.x;  p[g][1]=q0.y;  p[g][2]=q0.z;  p[g][3]=q0.w;
            p[g][4]=q1.x;  p[g][5]=q1.y;  p[g][6]=q1.z;  p[g][7]=q1.w;
            p[g][8]=q2.x;  p[g][9]=q2.y;  p[g][10]=q2.z; p[g][11]=q2.w;
            p[g][12]=q3.x; p[g][13]=q3.y; p[g][14]=q3.z; p[g][15]=q3.w;
        }
        if (has4) {
            const float4* r = reinterpret_cast<const float4*>(pb + (96 + lane) * 16);
            float4 q0 = __ldcg(r + 0), q1 = __ldcg(r + 1), q2 = __ldcg(r + 2), q3 = __ldcg(r + 3);
            p[3][0]=q0.x;  p[3][1]=q0.y;  p[3][2]=q0.z;  p[3][3]=q0.w;
            p[3][4]=q1.x;  p[3][5]=q1.y;  p[3][6]=q1.z;  p[3][7]=q1.w;
            p[3][8]=q2.x;  p[3][9]=q2.y;  p[3][10]=q2.z; p[3][11]=q2.w;
            p[3][12]=q3.x; p[3][13]=q3.y; p[3][14]=q3.z; p[3][15]=q3.w;
        }
        float lg0 = 0.f, lg1 = 0.f, lg2 = 0.f, lg3 = 0.f;
#pragma unroll
        for (int d = 0; d < 16; d++) {
            lg0 += p[0][d] * vsh[(lane      ) * 17 + d];
            lg1 += p[1][d] * vsh[(lane + 32 ) * 17 + d];
            lg2 += p[2][d] * vsh[(lane + 64 ) * 17 + d];
        }
        if (has4) {
#pragma unroll
            for (int d = 0; d < 16; d++) lg3 += p[3][d] * vsh[(96 + lane) * 17 + d];
        }
        float e0 = __expf(lg0), e1 = __expf(lg1), e2 = __expf(lg2);
        float e3 = has4 ? __expf(lg3) : 0.f;
        float tot = e0 + e1 + e2 + e3;
#pragma unroll
        for (int o = 16; o; o >>= 1) tot += __shfl_xor_sync(~0u, tot, o);
        float inv = 1.f / tot;
        float w0 = e0 * inv, w1 = e1 * inv, w2 = e2 * inv, w3 = e3 * inv;
#pragma unroll
        for (int d = 0; d < 16; d++) {
            sa[(lane      ) * 17 + d] += w0 * p[0][d];
            sa[(lane + 32 ) * 17 + d] += w1 * p[1][d];
            sa[(lane + 64 ) * 17 + d] += w2 * p[2][d];
        }
        if (has4) {
#pragma unroll
            for (int d = 0; d < 16; d++)
                sa[(96 + lane) * 17 + d] += w3 * p[3][d];
        }
    }
    __syncthreads();
    for (int idx = tid; idx < 1600; idx += 128) {
        int cc = idx >> 4, d = idx & 15;
        float s = sacc[0][cc * 17 + d] + sacc[1][cc * 17 + d]
                + sacc[2][cc * 17 + d] + sacc[3][cc * 17 + d];
        atomicAdd(&g_S[SOFF2 + 12800 + b * 1600 + idx], s);
    }

    __threadfence();
    __syncthreads();
    if (tid == 0) s_done = atomicAdd(&g_ctr[2], 1u);
    __syncthreads();
    if (s_done == 303u) {                            // last of 304 blocks
        __threadfence();
        for (int cap = tid; cap < 800; cap += 128)
            squash16(&g_S[SOFF2 + 12800 + cap * 16], 1.f, v2 + cap * 16);
        __syncthreads();
        for (int e = tid; e < 25600; e += 128) g_S[SOFF2 + e] = 0.f;
        if (tid == 0) g_ctr[2] = 0u;
    }
}

// ---------------------------------------------------------------------------
extern "C" void kernel_launch(void* const* d_in, const int* in_sizes, int n_in,
                              void* d_out, int out_size)
{
    const float* X  = (const float*)d_in[0];   // [8,1152,8]
    const float* W0 = (const float*)d_in[1];   // [1152,8,16,8]
    const float* W1 = (const float*)d_in[2];   // [584,20,16,16]
    const float* W2 = (const float*)d_in[3];   // [596,100,16,16]
    float* out = (float*)d_out;
    float* v0 = out;                 // [8][8][16]
    float* v1 = out + 1024;          // [8][20][16]
    float* v2 = out + 3584;          // [8][100][16]

    // ---- level 0 ----
    pred_kernel<1152, 8, 8, 4, 2, 8><<<dim3(144, 1), 512>>>(X, W0, X, 1152, 1, SOFF0);
    route0_kernel<<<dim3(19, 8), 256>>>(v0);

    // ---- level 1 ----
    pred_kernel<584, 20, 16, 2, 2, 20><<<dim3(146, 1), 640>>>(X, W1, v0, 576, 8, SOFF1);
    route1_kernel<<<dim3(20, 8), 256>>>(v1);

    // ---- level 2 ----
    pred_kernel<596, 100, 16, 1, 4, 50><<<dim3(149, 2), 800>>>(X, W2, v1, 576, 20, SOFF2);
    route2_kernel<<<dim3(38, 8), 128>>>(v2);
}

// round 12
// speedup vs baseline: 1.4844x; 1.2621x over previous
#include <cuda_runtime.h>
#include <cuda_fp16.h>
#include <math.h>

#define BATCH 8
#define DOUT  16

// ---------------------------------------------------------------------------
// Scratch (device globals -- no allocation allowed)
// ---------------------------------------------------------------------------
__device__ __half g_predh[(size_t)BATCH * 596 * 100 * DOUT];  // fp16 pred, 15.2 MB
// S regions (S | S2) per level, disjoint:
//   L0: [0,2048)   L1: [2048,7168)   L2: [7168,32768)
// INVARIANT: g_S all-zero at kernel_launch entry (BSS at init; each route
// kernel's tail block re-zeros its level's region after the final squash).
__device__ float g_S[32768];
__device__ unsigned g_ctr[4];   // zero-initialized; each use self-resets

#define SOFF0 0
#define SOFF1 2048
#define SOFF2 7168

// ---------------------------------------------------------------------------
// squash: v = (sq/(1+sq)) * s / sqrt(sq+eps), s = in*scale.
// ---------------------------------------------------------------------------
__device__ __forceinline__ void squash16(const float* __restrict__ s, float scale,
                                         float* __restrict__ out)
{
    float4 a[4];
    float sq = 0.f;
#pragma unroll
    for (int j = 0; j < 4; j++) {
        float4 t = __ldcg(reinterpret_cast<const float4*>(s) + j);
        t.x *= scale; t.y *= scale; t.z *= scale; t.w *= scale;
        sq += t.x*t.x + t.y*t.y + t.z*t.z + t.w*t.w;
        a[j] = t;
    }
    float f = sq / ((1.f + sq) * sqrtf(sq + 1e-7f));
#pragma unroll
    for (int j = 0; j < 4; j++) {
        a[j].x *= f; a[j].y *= f; a[j].z *= f; a[j].w *= f;
        reinterpret_cast<float4*>(out)[j] = a[j];
    }
}

__device__ __forceinline__ void squash16s(const float* __restrict__ s, float scale,
                                          float* __restrict__ out)   // scalar stores
{
    float a[16];
    float sq = 0.f;
#pragma unroll
    for (int j = 0; j < 4; j++) {
        float4 t = __ldcg(reinterpret_cast<const float4*>(s) + j);
        t.x *= scale; t.y *= scale; t.z *= scale; t.w *= scale;
        sq += t.x*t.x + t.y*t.y + t.z*t.z + t.w*t.w;
        a[4*j+0] = t.x; a[4*j+1] = t.y; a[4*j+2] = t.z; a[4*j+3] = t.w;
    }
    float f = sq / ((1.f + sq) * sqrtf(sq + 1e-7f));
#pragma unroll
    for (int j = 0; j < 16; j++) out[j] = a[j] * f;
}

// load 16 consecutive halves (32B-aligned) -> 16 floats
__device__ __forceinline__ void load_row16h(const __half* __restrict__ p,
                                            float* __restrict__ out)
{
    float4 q0 = __ldcg(reinterpret_cast<const float4*>(p));
    float4 q1 = __ldcg(reinterpret_cast<const float4*>(p) + 1);
    const __half2* h0 = reinterpret_cast<const __half2*>(&q0);
    const __half2* h1 = reinterpret_cast<const __half2*>(&q1);
#pragma unroll
    for (int j = 0; j < 4; j++) {
        float2 f = __half22float2(h0[j]);
        out[2*j]     = f.x;
        out[2*j + 1] = f.y;
    }
#pragma unroll
    for (int j = 0; j < 4; j++) {
        float2 f = __half22float2(h1[j]);
        out[8 + 2*j]     = f.x;
        out[8 + 2*j + 1] = f.y;
    }
}

// ---------------------------------------------------------------------------
// pred[b,i,c,d] = sum_k W[i,c,d,k] * Xlvl[b,i,k]   (stored fp16)
// also accumulates S[b,c,d] += sum_i pred  (fp32 register acc + 1 atomic/thread/b)
// ---------------------------------------------------------------------------
template<int N, int C, int K, int IPAR, int ILOOP, int CTILE>
__global__ __launch_bounds__(IPAR * CTILE * DOUT)
void pred_kernel(const float* __restrict__ X,
                 const float* __restrict__ W,
                 const float* __restrict__ Vprev,
                 int skip, int cprev, int soff)
{
    constexpr int ICHUNK = IPAR * ILOOP;
    constexpr int TPB    = IPAR * CTILE * DOUT;
    constexpr int K4     = K / 4;
    __shared__ float Xs[ICHUNK][BATCH][K];

    const int tid = threadIdx.x;
    const int i0  = blockIdx.x * ICHUNK;

    for (int idx = tid; idx < ICHUNK * BATCH * K; idx += TPB) {
        int il = idx / (BATCH * K);
        int r  = idx % (BATCH * K);
        int b  = r / K, k = r % K;
        int gi = i0 + il;
        float v;
        if (gi < skip) v = X[b * 9216 + gi * K + k];
        else           v = Vprev[(b * cprev + (gi - skip)) * DOUT + k];
        Xs[il][b][k] = v;
    }
    __syncthreads();

    const int isub  = tid / (CTILE * DOUT);
    const int rem   = tid % (CTILE * DOUT);
    const int c     = blockIdx.y * CTILE + rem / DOUT;
    const int d     = rem % DOUT;
    const int ibase = isub * ILOOP;

    float acc[BATCH];
#pragma unroll
    for (int b = 0; b < BATCH; b++) acc[b] = 0.f;

    float4 wc[K4];
    {
        const float* wp = W + ((size_t)((i0 + ibase) * C + c) * DOUT + d) * K;
#pragma unroll
        for (int k4 = 0; k4 < K4; k4++)
            wc[k4] = __ldcg(reinterpret_cast<const float4*>(wp) + k4);
    }

#pragma unroll
    for (int il2 = 0; il2 < ILOOP; ++il2) {
        float4 wn[K4];
        if (il2 + 1 < ILOOP) {
            const float* wp =
                W + ((size_t)((i0 + ibase + il2 + 1) * C + c) * DOUT + d) * K;
#pragma unroll
            for (int k4 = 0; k4 < K4; k4++)
                wn[k4] = __ldcg(reinterpret_cast<const float4*>(wp) + k4);
        }
        const int iloc = ibase + il2;
        const int i    = i0 + iloc;
        float w[K];
#pragma unroll
        for (int k4 = 0; k4 < K4; k4++) {
            w[4*k4+0] = wc[k4].x; w[4*k4+1] = wc[k4].y;
            w[4*k4+2] = wc[k4].z; w[4*k4+3] = wc[k4].w;
        }
#pragma unroll
        for (int b = 0; b < BATCH; b++) {
            float p = 0.f;
#pragma unroll
            for (int k = 0; k < K; k++) p += w[k] * Xs[iloc][b][k];
            acc[b] += p;
            g_predh[(((size_t)b * N + i) * C + c) * DOUT + d] = __float2half_rn(p);
        }
#pragma unroll
        for (int k4 = 0; k4 < K4; k4++) wc[k4] = wn[k4];
    }
#pragma unroll
    for (int b = 0; b < BATCH; b++)
        atomicAdd(&g_S[soff + (b * C + c) * DOUT + d], acc[b]);
}

// ---------------------------------------------------------------------------
// route level 0: C=8, CD=128, N=1152.  grid (19, 8), block 256 (152 warps/b).
// lane holds 4 (c,d) elems (2x half2 = 8B/lane, coalesced); unroll-2
// interleaved i-pairs; no-max softmax (logits bounded).
// ---------------------------------------------------------------------------
__global__ __launch_bounds__(256) void route0_kernel(float* __restrict__ v0)
{
    __shared__ float vsh[128];
    __shared__ unsigned s_done;
    const int tid = threadIdx.x, lane = tid & 31, warp = tid >> 5;
    const int b = blockIdx.y;

    if (tid < 8)
        squash16(&g_S[SOFF0 + b * 128 + tid * 16], 0.125f, &vsh[tid * 16]);
    __syncthreads();

    const float4 v4 = *reinterpret_cast<const float4*>(&vsh[lane * 4]);
    float ax = 0.f, ay = 0.f, az = 0.f, aw = 0.f;
    const int wg = blockIdx.x * 8 + warp;           // 0..151 per b
    const __half* base = g_predh + (size_t)b * 1152 * 128;

    int i = wg;
    for (; i + 152 < 1152; i += 304) {
        const __half2* hA = reinterpret_cast<const __half2*>(base + (size_t)i * 128) + lane * 2;
        const __half2* hB = reinterpret_cast<const __half2*>(base + (size_t)(i + 152) * 128) + lane * 2;
        float2 a0 = __half22float2(__ldcg(hA)), a1 = __half22float2(__ldcg(hA + 1));
        float2 b0 = __half22float2(__ldcg(hB)), b1 = __half22float2(__ldcg(hB + 1));
        float lgA = a0.x*v4.x + a0.y*v4.y + a1.x*v4.z + a1.y*v4.w;
        float lgB = b0.x*v4.x + b0.y*v4.y + b1.x*v4.z + b1.y*v4.w;
        lgA += __shfl_xor_sync(~0u, lgA, 1);  lgB += __shfl_xor_sync(~0u, lgB, 1);
        lgA += __shfl_xor_sync(~0u, lgA, 2);  lgB += __shfl_xor_sync(~0u, lgB, 2);
        float eA = __expf(lgA), eB = __expf(lgB);
        float sA = eA, sB = eB;
        sA += __shfl_xor_sync(~0u, sA, 4);   sB += __shfl_xor_sync(~0u, sB, 4);
        sA += __shfl_xor_sync(~0u, sA, 8);   sB += __shfl_xor_sync(~0u, sB, 8);
        sA += __shfl_xor_sync(~0u, sA, 16);  sB += __shfl_xor_sync(~0u, sB, 16);
        float wA = eA / sA, wB = eB / sB;
        ax += wA * a0.x + wB * b0.x;  ay += wA * a0.y + wB * b0.y;
        az += wA * a1.x + wB * b1.x;  aw += wA * a1.y + wB * b1.y;
    }
    if (i < 1152) {
        const __half2* hA = reinterpret_cast<const __half2*>(base + (size_t)i * 128) + lane * 2;
        float2 a0 = __half22float2(__ldcg(hA)), a1 = __half22float2(__ldcg(hA + 1));
        float lg = a0.x*v4.x + a0.y*v4.y + a1.x*v4.z + a1.y*v4.w;
        lg += __shfl_xor_sync(~0u, lg, 1);
        lg += __shfl_xor_sync(~0u, lg, 2);
        float e = __expf(lg);
        float s = e;
        s += __shfl_xor_sync(~0u, s, 4);
        s += __shfl_xor_sync(~0u, s, 8);
        s += __shfl_xor_sync(~0u, s, 16);
        float w = e / s;
        ax += w * a0.x; ay += w * a0.y; az += w * a1.x; aw += w * a1.y;
    }
    float* S2 = &g_S[SOFF0 + 1024 + b * 128 + lane * 4];
    atomicAdd(S2 + 0, ax); atomicAdd(S2 + 1, ay);
    atomicAdd(S2 + 2, az); atomicAdd(S2 + 3, aw);

    __threadfence();
    __syncthreads();
    if (tid == 0) s_done = atomicAdd(&g_ctr[0], 1u);
    __syncthreads();
    if (s_done == 151u) {                            // last of 152 blocks
        __threadfence();
        if (tid < 64)
            squash16(&g_S[SOFF0 + 1024 + tid * 16], 1.f, v0 + tid * 16);
        __syncthreads();
        for (int e = tid; e < 2048; e += 256) g_S[SOFF0 + e] = 0.f;
        if (tid == 0) g_ctr[0] = 0u;
    }
}

// ---------------------------------------------------------------------------
// route level 1: C=20, CD=320, N=584.  grid (20, 8), block 256 (160 warps/b).
// Proven R6 layout (element 32*cc+lane; c = 2*cc+lane/16, d = lane%16) with
// fp16 loads and unroll-2 interleaving of the two shfl/exp chains.
// ---------------------------------------------------------------------------
__global__ __launch_bounds__(256) void route1_kernel(float* __restrict__ v1)
{
    __shared__ float vsh[320];
    __shared__ unsigned s_done;
    const int tid = threadIdx.x, lane = tid & 31, warp = tid >> 5;
    const int b = blockIdx.y;

    if (tid < 20)
        squash16(&g_S[SOFF1 + b * 320 + tid * 16], 0.05f, &vsh[tid * 16]);
    __syncthreads();

    float v[10], acc[10];
#pragma unroll
    for (int cc = 0; cc < 10; cc++) { v[cc] = vsh[32 * cc + lane]; acc[cc] = 0.f; }

    const __half* base = g_predh + (size_t)b * 584 * 320;
    const int wg = blockIdx.x * 8 + warp;           // 0..159 per b

    int i = wg;
    for (; i + 160 < 584; i += 320) {
        const __half* pA = base + (size_t)i * 320;
        const __half* pB = base + (size_t)(i + 160) * 320;
        float a[10], c2[10], lgA[10], lgB[10];
#pragma unroll
        for (int cc = 0; cc < 10; cc++) {
            a[cc]  = __half2float(__ldcg(pA + 32 * cc + lane));
            c2[cc] = __half2float(__ldcg(pB + 32 * cc + lane));
            float tA = a[cc] * v[cc];
            float tB = c2[cc] * v[cc];
            tA += __shfl_xor_sync(~0u, tA, 1);  tB += __shfl_xor_sync(~0u, tB, 1);
            tA += __shfl_xor_sync(~0u, tA, 2);  tB += __shfl_xor_sync(~0u, tB, 2);
            tA += __shfl_xor_sync(~0u, tA, 4);  tB += __shfl_xor_sync(~0u, tB, 4);
            tA += __shfl_xor_sync(~0u, tA, 8);  tB += __shfl_xor_sync(~0u, tB, 8);
            lgA[cc] = tA; lgB[cc] = tB;
        }
        float totA = 0.f, totB = 0.f;
#pragma unroll
        for (int cc = 0; cc < 10; cc++) {
            lgA[cc] = __expf(lgA[cc]); totA += lgA[cc];
            lgB[cc] = __expf(lgB[cc]); totB += lgB[cc];
        }
        totA += __shfl_xor_sync(~0u, totA, 16);
        totB += __shfl_xor_sync(~0u, totB, 16);
        float invA = 1.f / totA, invB = 1.f / totB;
#pragma unroll
        for (int cc = 0; cc < 10; cc++)
            acc[cc] += lgA[cc] * invA * a[cc] + lgB[cc] * invB * c2[cc];
    }
    if (i < 584) {
        const __half* pA = base + (size_t)i * 320;
        float a[10], lg[10];
#pragma unroll
        for (int cc = 0; cc < 10; cc++) {
            a[cc] = __half2float(__ldcg(pA + 32 * cc + lane));
            float t = a[cc] * v[cc];
            t += __shfl_xor_sync(~0u, t, 1);
            t += __shfl_xor_sync(~0u, t, 2);
            t += __shfl_xor_sync(~0u, t, 4);
            t += __shfl_xor_sync(~0u, t, 8);
            lg[cc] = t;
        }
        float tot = 0.f;
#pragma unroll
        for (int cc = 0; cc < 10; cc++) { lg[cc] = __expf(lg[cc]); tot += lg[cc]; }
        tot += __shfl_xor_sync(~0u, tot, 16);
        float inv = 1.f / tot;
#pragma unroll
        for (int cc = 0; cc < 10; cc++) acc[cc] += lg[cc] * inv * a[cc];
    }
#pragma unroll
    for (int cc = 0; cc < 10; cc++)
        atomicAdd(&g_S[SOFF1 + 2560 + b * 320 + 32 * cc + lane], acc[cc]);

    __threadfence();
    __syncthreads();
    if (tid == 0) s_done = atomicAdd(&g_ctr[1], 1u);
    __syncthreads();
    if (s_done == 159u) {                            // last of 160 blocks
        __threadfence();
        if (tid < 160)
            squash16(&g_S[SOFF1 + 2560 + tid * 16], 1.f, v1 + tid * 16);
        __syncthreads();
        for (int e = tid; e < 5120; e += 256) g_S[SOFF1 + e] = 0.f;
        if (tid == 0) g_ctr[1] = 0u;
    }
}

// ---------------------------------------------------------------------------
// route level 2: C=100, N=596.  grid (38, 8), block 128 (152 warps/b).
// LANE-OWNS-CAPSULE: lane owns c = lane, lane+32, lane+64 (+96 for lane<4);
// fp16 rows (32B each, 2x 16B loads); local dots vs pad-17 smem v; 5 shfls/i;
// per-warp pad-17 smem accumulators (race-free: one lane per row).
// ---------------------------------------------------------------------------
__global__ __launch_bounds__(128) void route2_kernel(float* __restrict__ v2)
{
    __shared__ float vsh[100 * 17];
    __shared__ float sacc[4][100 * 17];
    __shared__ unsigned s_done;
    const int tid = threadIdx.x, lane = tid & 31, warp = tid >> 5;
    const int b = blockIdx.y;
    const bool has4 = lane < 4;

    if (tid < 100)
        squash16s(&g_S[SOFF2 + b * 1600 + tid * 16], 0.01f, &vsh[tid * 17]);
    for (int e = tid; e < 4 * 1700; e += 128) (&sacc[0][0])[e] = 0.f;
    __syncthreads();

    float* sa = sacc[warp];
    const int wg = blockIdx.x * 4 + warp;           // 0..151 per b
    const __half* pb_base = g_predh + (size_t)b * 596 * 1600;

    for (int i = wg; i < 596; i += 152) {
        const __half* pb = pb_base + (size_t)i * 1600;
        float p[4][16];
#pragma unroll
        for (int g = 0; g < 3; g++)
            load_row16h(pb + (lane + 32 * g) * 16, p[g]);
        if (has4)
            load_row16h(pb + (96 + lane) * 16, p[3]);

        float lg0 = 0.f, lg1 = 0.f, lg2 = 0.f, lg3 = 0.f;
#pragma unroll
        for (int d = 0; d < 16; d++) {
            lg0 += p[0][d] * vsh[(lane      ) * 17 + d];
            lg1 += p[1][d] * vsh[(lane + 32 ) * 17 + d];
            lg2 += p[2][d] * vsh[(lane + 64 ) * 17 + d];
        }
        if (has4) {
#pragma unroll
            for (int d = 0; d < 16; d++) lg3 += p[3][d] * vsh[(96 + lane) * 17 + d];
        }
        float e0 = __expf(lg0), e1 = __expf(lg1), e2 = __expf(lg2);
        float e3 = has4 ? __expf(lg3) : 0.f;
        float tot = e0 + e1 + e2 + e3;
#pragma unroll
        for (int o = 16; o; o >>= 1) tot += __shfl_xor_sync(~0u, tot, o);
        float inv = 1.f / tot;
        float w0 = e0 * inv, w1 = e1 * inv, w2 = e2 * inv, w3 = e3 * inv;
#pragma unroll
        for (int d = 0; d < 16; d++) {
            sa[(lane      ) * 17 + d] += w0 * p[0][d];
            sa[(lane + 32 ) * 17 + d] += w1 * p[1][d];
            sa[(lane + 64 ) * 17 + d] += w2 * p[2][d];
        }
        if (has4) {
#pragma unroll
            for (int d = 0; d < 16; d++)
                sa[(96 + lane) * 17 + d] += w3 * p[3][d];
        }
    }
    __syncthreads();
    for (int idx = tid; idx < 1600; idx += 128) {
        int cc = idx >> 4, d = idx & 15;
        float s = sacc[0][cc * 17 + d] + sacc[1][cc * 17 + d]
                + sacc[2][cc * 17 + d] + sacc[3][cc * 17 + d];
        atomicAdd(&g_S[SOFF2 + 12800 + b * 1600 + idx], s);
    }

    __threadfence();
    __syncthreads();
    if (tid == 0) s_done = atomicAdd(&g_ctr[2], 1u);
    __syncthreads();
    if (s_done == 303u) {                            // last of 304 blocks
        __threadfence();
        for (int cap = tid; cap < 800; cap += 128)
            squash16(&g_S[SOFF2 + 12800 + cap * 16], 1.f, v2 + cap * 16);
        __syncthreads();
        for (int e = tid; e < 25600; e += 128) g_S[SOFF2 + e] = 0.f;
        if (tid == 0) g_ctr[2] = 0u;
    }
}

// ---------------------------------------------------------------------------
extern "C" void kernel_launch(void* const* d_in, const int* in_sizes, int n_in,
                              void* d_out, int out_size)
{
    const float* X  = (const float*)d_in[0];   // [8,1152,8]
    const float* W0 = (const float*)d_in[1];   // [1152,8,16,8]
    const float* W1 = (const float*)d_in[2];   // [584,20,16,16]
    const float* W2 = (const float*)d_in[3];   // [596,100,16,16]
    float* out = (float*)d_out;
    float* v0 = out;                 // [8][8][16]
    float* v1 = out + 1024;          // [8][20][16]
    float* v2 = out + 3584;          // [8][100][16]

    // ---- level 0 ----
    pred_kernel<1152, 8, 8, 4, 2, 8><<<dim3(144, 1), 512>>>(X, W0, X, 1152, 1, SOFF0);
    route0_kernel<<<dim3(19, 8), 256>>>(v0);

    // ---- level 1 ----
    pred_kernel<584, 20, 16, 2, 2, 20><<<dim3(146, 1), 640>>>(X, W1, v0, 576, 8, SOFF1);
    route1_kernel<<<dim3(20, 8), 256>>>(v1);

    // ---- level 2 ----
    pred_kernel<596, 100, 16, 1, 4, 50><<<dim3(149, 2), 800>>>(X, W2, v1, 576, 20, SOFF2);
    route2_kernel<<<dim3(38, 8), 128>>>(v2);
}

// round 13
// speedup vs baseline: 1.5255x; 1.0277x over previous
#include <cuda_runtime.h>
#include <cuda_fp16.h>
#include <math.h>

#define BATCH 8
#define DOUT  16

// ---------------------------------------------------------------------------
// Scratch (device globals -- no allocation allowed)
// ---------------------------------------------------------------------------
__device__ __half g_predh[(size_t)BATCH * 596 * 100 * DOUT];  // fp16 pred, 15.2 MB
// S regions (S | S2) per level, disjoint:
//   L0: [0,2048)   L1: [2048,7168)   L2: [7168,32768)
// INVARIANT: g_S all-zero at kernel_launch entry.  Re-zeroing schedule:
//   L0 zeroed by route1 block(0,0)   (strictly after pred1 consumed S2_L0)
//   L1 zeroed by route2 block(0,0)   (strictly after pred2 consumed S2_L1)
//   L2 zeroed by route2 election tail
__device__ float g_S[32768];
__device__ unsigned g_ctr[4];   // zero-initialized; route2 tail self-resets

#define SOFF0 0
#define SOFF1 2048
#define SOFF2 7168

// ---------------------------------------------------------------------------
// squash: v = (sq/(1+sq)) * s / sqrt(sq+eps), s = in*scale.
// ---------------------------------------------------------------------------
__device__ __forceinline__ void squash16(const float* __restrict__ s, float scale,
                                         float* __restrict__ out)
{
    float4 a[4];
    float sq = 0.f;
#pragma unroll
    for (int j = 0; j < 4; j++) {
        float4 t = __ldcg(reinterpret_cast<const float4*>(s) + j);
        t.x *= scale; t.y *= scale; t.z *= scale; t.w *= scale;
        sq += t.x*t.x + t.y*t.y + t.z*t.z + t.w*t.w;
        a[j] = t;
    }
    float f = sq / ((1.f + sq) * sqrtf(sq + 1e-7f));
#pragma unroll
    for (int j = 0; j < 4; j++) {
        a[j].x *= f; a[j].y *= f; a[j].z *= f; a[j].w *= f;
        reinterpret_cast<float4*>(out)[j] = a[j];
    }
}

__device__ __forceinline__ void squash16s(const float* __restrict__ s, float scale,
                                          float* __restrict__ out)   // scalar stores
{
    float a[16];
    float sq = 0.f;
#pragma unroll
    for (int j = 0; j < 4; j++) {
        float4 t = __ldcg(reinterpret_cast<const float4*>(s) + j);
        t.x *= scale; t.y *= scale; t.z *= scale; t.w *= scale;
        sq += t.x*t.x + t.y*t.y + t.z*t.z + t.w*t.w;
        a[4*j+0] = t.x; a[4*j+1] = t.y; a[4*j+2] = t.z; a[4*j+3] = t.w;
    }
    float f = sq / ((1.f + sq) * sqrtf(sq + 1e-7f));
#pragma unroll
    for (int j = 0; j < 16; j++) out[j] = a[j] * f;
}

// load 16 consecutive halves (32B-aligned) -> 16 floats
__device__ __forceinline__ void load_row16h(const __half* __restrict__ p,
                                            float* __restrict__ out)
{
    float4 q0 = __ldcg(reinterpret_cast<const float4*>(p));
    float4 q1 = __ldcg(reinterpret_cast<const float4*>(p) + 1);
    const __half2* h0 = reinterpret_cast<const __half2*>(&q0);
    const __half2* h1 = reinterpret_cast<const __half2*>(&q1);
#pragma unroll
    for (int j = 0; j < 4; j++) {
        float2 f = __half22float2(h0[j]);
        out[2*j]     = f.x;
        out[2*j + 1] = f.y;
    }
#pragma unroll
    for (int j = 0; j < 4; j++) {
        float2 f = __half22float2(h1[j]);
        out[8 + 2*j]     = f.x;
        out[8 + 2*j + 1] = f.y;
    }
}

// ---------------------------------------------------------------------------
// pred[b,i,c,d] = sum_k W[i,c,d,k] * Xlvl[b,i,k]   (stored fp16)
// + S[b,c,d] accumulation (fp32 register acc + 1 atomic/thread/b).
// CPREV>0: input capsules i>=skip come from squash(S2_prev), computed INLINE
// into smem by blocks whose i-range touches them (kernel boundary orders the
// previous route's atomics before our reads). The block with i0==skip also
// writes the squashed v to gmem (the level's output).
// ---------------------------------------------------------------------------
template<int N, int C, int K, int IPAR, int ILOOP, int CTILE, int CPREV>
__global__ __launch_bounds__(IPAR * CTILE * DOUT)
void pred_kernel(const float* __restrict__ X,
                 const float* __restrict__ W,
                 int skip, int soff, int sprev, float* __restrict__ vout)
{
    constexpr int ICHUNK = IPAR * ILOOP;
    constexpr int TPB    = IPAR * CTILE * DOUT;
    constexpr int K4     = K / 4;
    __shared__ float Xs[ICHUNK][BATCH][K];
    __shared__ float vbuf[CPREV > 0 ? CPREV * BATCH * DOUT : 1];

    const int tid = threadIdx.x;
    const int i0  = blockIdx.x * ICHUNK;

    if constexpr (CPREV > 0) {
        if (i0 + ICHUNK > skip) {               // block-uniform branch
            for (int t = tid; t < CPREV * BATCH; t += TPB)
                squash16(&g_S[sprev + t * 16], 1.f, &vbuf[t * 16]);
            __syncthreads();
            if (i0 == skip && blockIdx.y == 0)  // this level's v output
                for (int e = tid; e < CPREV * BATCH * DOUT; e += TPB)
                    vout[e] = vbuf[e];
        }
    }

    for (int idx = tid; idx < ICHUNK * BATCH * K; idx += TPB) {
        int il = idx / (BATCH * K);
        int r  = idx % (BATCH * K);
        int b  = r / K, k = r % K;
        int gi = i0 + il;
        float v;
        if (gi < skip) v = X[b * 9216 + gi * K + k];
        else if constexpr (CPREV > 0) v = vbuf[(b * CPREV + (gi - skip)) * DOUT + k];
        else v = 0.f;
        Xs[il][b][k] = v;
    }
    __syncthreads();

    const int isub  = tid / (CTILE * DOUT);
    const int rem   = tid % (CTILE * DOUT);
    const int c     = blockIdx.y * CTILE + rem / DOUT;
    const int d     = rem % DOUT;
    const int ibase = isub * ILOOP;

    float acc[BATCH];
#pragma unroll
    for (int b = 0; b < BATCH; b++) acc[b] = 0.f;

    float4 wc[K4];
    {
        const float* wp = W + ((size_t)((i0 + ibase) * C + c) * DOUT + d) * K;
#pragma unroll
        for (int k4 = 0; k4 < K4; k4++)
            wc[k4] = __ldcg(reinterpret_cast<const float4*>(wp) + k4);
    }

#pragma unroll
    for (int il2 = 0; il2 < ILOOP; ++il2) {
        float4 wn[K4];
        if (il2 + 1 < ILOOP) {
            const float* wp =
                W + ((size_t)((i0 + ibase + il2 + 1) * C + c) * DOUT + d) * K;
#pragma unroll
            for (int k4 = 0; k4 < K4; k4++)
                wn[k4] = __ldcg(reinterpret_cast<const float4*>(wp) + k4);
        }
        const int iloc = ibase + il2;
        const int i    = i0 + iloc;
        float w[K];
#pragma unroll
        for (int k4 = 0; k4 < K4; k4++) {
            w[4*k4+0] = wc[k4].x; w[4*k4+1] = wc[k4].y;
            w[4*k4+2] = wc[k4].z; w[4*k4+3] = wc[k4].w;
        }
#pragma unroll
        for (int b = 0; b < BATCH; b++) {
            float p = 0.f;
#pragma unroll
            for (int k = 0; k < K; k++) p += w[k] * Xs[iloc][b][k];
            acc[b] += p;
            g_predh[(((size_t)b * N + i) * C + c) * DOUT + d] = __float2half_rn(p);
        }
#pragma unroll
        for (int k4 = 0; k4 < K4; k4++) wc[k4] = wn[k4];
    }
#pragma unroll
    for (int b = 0; b < BATCH; b++)
        atomicAdd(&g_S[soff + (b * C + c) * DOUT + d], acc[b]);
}

// ---------------------------------------------------------------------------
// route level 0: C=8, CD=128, N=1152.  grid (19, 8), block 256.
// NO TAIL: ends at its S2 atomics; pred1 does the squash.
// ---------------------------------------------------------------------------
__global__ __launch_bounds__(256) void route0_kernel()
{
    __shared__ float vsh[128];
    const int tid = threadIdx.x, lane = tid & 31, warp = tid >> 5;
    const int b = blockIdx.y;

    if (tid < 8)
        squash16(&g_S[SOFF0 + b * 128 + tid * 16], 0.125f, &vsh[tid * 16]);
    __syncthreads();

    const float4 v4 = *reinterpret_cast<const float4*>(&vsh[lane * 4]);
    float ax = 0.f, ay = 0.f, az = 0.f, aw = 0.f;
    const int wg = blockIdx.x * 8 + warp;           // 0..151 per b
    const __half* base = g_predh + (size_t)b * 1152 * 128;

    int i = wg;
    for (; i + 152 < 1152; i += 304) {
        const __half2* hA = reinterpret_cast<const __half2*>(base + (size_t)i * 128) + lane * 2;
        const __half2* hB = reinterpret_cast<const __half2*>(base + (size_t)(i + 152) * 128) + lane * 2;
        float2 a0 = __half22float2(__ldcg(hA)), a1 = __half22float2(__ldcg(hA + 1));
        float2 b0 = __half22float2(__ldcg(hB)), b1 = __half22float2(__ldcg(hB + 1));
        float lgA = a0.x*v4.x + a0.y*v4.y + a1.x*v4.z + a1.y*v4.w;
        float lgB = b0.x*v4.x + b0.y*v4.y + b1.x*v4.z + b1.y*v4.w;
        lgA += __shfl_xor_sync(~0u, lgA, 1);  lgB += __shfl_xor_sync(~0u, lgB, 1);
        lgA += __shfl_xor_sync(~0u, lgA, 2);  lgB += __shfl_xor_sync(~0u, lgB, 2);
        float eA = __expf(lgA), eB = __expf(lgB);
        float sA = eA, sB = eB;
        sA += __shfl_xor_sync(~0u, sA, 4);   sB += __shfl_xor_sync(~0u, sB, 4);
        sA += __shfl_xor_sync(~0u, sA, 8);   sB += __shfl_xor_sync(~0u, sB, 8);
        sA += __shfl_xor_sync(~0u, sA, 16);  sB += __shfl_xor_sync(~0u, sB, 16);
        float wA = eA / sA, wB = eB / sB;
        ax += wA * a0.x + wB * b0.x;  ay += wA * a0.y + wB * b0.y;
        az += wA * a1.x + wB * b1.x;  aw += wA * a1.y + wB * b1.y;
    }
    if (i < 1152) {
        const __half2* hA = reinterpret_cast<const __half2*>(base + (size_t)i * 128) + lane * 2;
        float2 a0 = __half22float2(__ldcg(hA)), a1 = __half22float2(__ldcg(hA + 1));
        float lg = a0.x*v4.x + a0.y*v4.y + a1.x*v4.z + a1.y*v4.w;
        lg += __shfl_xor_sync(~0u, lg, 1);
        lg += __shfl_xor_sync(~0u, lg, 2);
        float e = __expf(lg);
        float s = e;
        s += __shfl_xor_sync(~0u, s, 4);
        s += __shfl_xor_sync(~0u, s, 8);
        s += __shfl_xor_sync(~0u, s, 16);
        float w = e / s;
        ax += w * a0.x; ay += w * a0.y; az += w * a1.x; aw += w * a1.y;
    }
    float* S2 = &g_S[SOFF0 + 1024 + b * 128 + lane * 4];
    atomicAdd(S2 + 0, ax); atomicAdd(S2 + 1, ay);
    atomicAdd(S2 + 2, az); atomicAdd(S2 + 3, aw);
}

// ---------------------------------------------------------------------------
// route level 1: C=20, CD=320, N=584.  grid (20, 8), block 256.
// NO TAIL (pred2 does the squash).  Block (0,0) re-zeros the L0 region
// (safe: runs strictly after pred1 consumed S2_L0; route1 never reads L0).
// ---------------------------------------------------------------------------
__global__ __launch_bounds__(256) void route1_kernel()
{
    __shared__ float vsh[320];
    const int tid = threadIdx.x, lane = tid & 31, warp = tid >> 5;
    const int b = blockIdx.y;

    if (tid < 20)
        squash16(&g_S[SOFF1 + b * 320 + tid * 16], 0.05f, &vsh[tid * 16]);
    __syncthreads();

    if (blockIdx.x == 0 && blockIdx.y == 0)
        for (int e = tid; e < 2048; e += 256) g_S[SOFF0 + e] = 0.f;

    float v[10], acc[10];
#pragma unroll
    for (int cc = 0; cc < 10; cc++) { v[cc] = vsh[32 * cc + lane]; acc[cc] = 0.f; }

    const __half* base = g_predh + (size_t)b * 584 * 320;
    const int wg = blockIdx.x * 8 + warp;           // 0..159 per b

    int i = wg;
    for (; i + 160 < 584; i += 320) {
        const __half* pA = base + (size_t)i * 320;
        const __half* pB = base + (size_t)(i + 160) * 320;
        float a[10], c2[10], lgA[10], lgB[10];
#pragma unroll
        for (int cc = 0; cc < 10; cc++) {
            a[cc]  = __half2float(__ldcg(pA + 32 * cc + lane));
            c2[cc] = __half2float(__ldcg(pB + 32 * cc + lane));
            float tA = a[cc] * v[cc];
            float tB = c2[cc] * v[cc];
            tA += __shfl_xor_sync(~0u, tA, 1);  tB += __shfl_xor_sync(~0u, tB, 1);
            tA += __shfl_xor_sync(~0u, tA, 2);  tB += __shfl_xor_sync(~0u, tB, 2);
            tA += __shfl_xor_sync(~0u, tA, 4);  tB += __shfl_xor_sync(~0u, tB, 4);
            tA += __shfl_xor_sync(~0u, tA, 8);  tB += __shfl_xor_sync(~0u, tB, 8);
            lgA[cc] = tA; lgB[cc] = tB;
        }
        float totA = 0.f, totB = 0.f;
#pragma unroll
        for (int cc = 0; cc < 10; cc++) {
            lgA[cc] = __expf(lgA[cc]); totA += lgA[cc];
            lgB[cc] = __expf(lgB[cc]); totB += lgB[cc];
        }
        totA += __shfl_xor_sync(~0u, totA, 16);
        totB += __shfl_xor_sync(~0u, totB, 16);
        float invA = 1.f / totA, invB = 1.f / totB;
#pragma unroll
        for (int cc = 0; cc < 10; cc++)
            acc[cc] += lgA[cc] * invA * a[cc] + lgB[cc] * invB * c2[cc];
    }
    if (i < 584) {
        const __half* pA = base + (size_t)i * 320;
        float a[10], lg[10];
#pragma unroll
        for (int cc = 0; cc < 10; cc++) {
            a[cc] = __half2float(__ldcg(pA + 32 * cc + lane));
            float t = a[cc] * v[cc];
            t += __shfl_xor_sync(~0u, t, 1);
            t += __shfl_xor_sync(~0u, t, 2);
            t += __shfl_xor_sync(~0u, t, 4);
            t += __shfl_xor_sync(~0u, t, 8);
            lg[cc] = t;
        }
        float tot = 0.f;
#pragma unroll
        for (int cc = 0; cc < 10; cc++) { lg[cc] = __expf(lg[cc]); tot += lg[cc]; }
        tot += __shfl_xor_sync(~0u, tot, 16);
        float inv = 1.f / tot;
#pragma unroll
        for (int cc = 0; cc < 10; cc++) acc[cc] += lg[cc] * inv * a[cc];
    }
#pragma unroll
    for (int cc = 0; cc < 10; cc++)
        atomicAdd(&g_S[SOFF1 + 2560 + b * 320 + 32 * cc + lane], acc[cc]);
}

// ---------------------------------------------------------------------------
// route level 2: C=100, N=596.  grid (38, 8), block 128.
// LANE-OWNS-CAPSULE (proven in R11/R12).  Block (0,0) re-zeros L1.
// Keeps the ONLY election tail: v2 squash + zero L2 + ctr reset.
// ---------------------------------------------------------------------------
__global__ __launch_bounds__(128) void route2_kernel(float* __restrict__ v2)
{
    __shared__ float vsh[100 * 17];
    __shared__ float sacc[4][100 * 17];
    __shared__ unsigned s_done;
    const int tid = threadIdx.x, lane = tid & 31, warp = tid >> 5;
    const int b = blockIdx.y;
    const bool has4 = lane < 4;

    if (tid < 100)
        squash16s(&g_S[SOFF2 + b * 1600 + tid * 16], 0.01f, &vsh[tid * 17]);
    for (int e = tid; e < 4 * 1700; e += 128) (&sacc[0][0])[e] = 0.f;
    __syncthreads();

    if (blockIdx.x == 0 && blockIdx.y == 0)
        for (int e = tid; e < 5120; e += 128) g_S[SOFF1 + e] = 0.f;

    float* sa = sacc[warp];
    const int wg = blockIdx.x * 4 + warp;           // 0..151 per b
    const __half* pb_base = g_predh + (size_t)b * 596 * 1600;

    for (int i = wg; i < 596; i += 152) {
        const __half* pb = pb_base + (size_t)i * 1600;
        float p[4][16];
#pragma unroll
        for (int g = 0; g < 3; g++)
            load_row16h(pb + (lane + 32 * g) * 16, p[g]);
        if (has4)
            load_row16h(pb + (96 + lane) * 16, p[3]);

        float lg0 = 0.f, lg1 = 0.f, lg2 = 0.f, lg3 = 0.f;
#pragma unroll
        for (int d = 0; d < 16; d++) {
            lg0 += p[0][d] * vsh[(lane      ) * 17 + d];
            lg1 += p[1][d] * vsh[(lane + 32 ) * 17 + d];
            lg2 += p[2][d] * vsh[(lane + 64 ) * 17 + d];
        }
        if (has4) {
#pragma unroll
            for (int d = 0; d < 16; d++) lg3 += p[3][d] * vsh[(96 + lane) * 17 + d];
        }
        float e0 = __expf(lg0), e1 = __expf(lg1), e2 = __expf(lg2);
        float e3 = has4 ? __expf(lg3) : 0.f;
        float tot = e0 + e1 + e2 + e3;
#pragma unroll
        for (int o = 16; o; o >>= 1) tot += __shfl_xor_sync(~0u, tot, o);
        float inv = 1.f / tot;
        float w0 = e0 * inv, w1 = e1 * inv, w2 = e2 * inv, w3 = e3 * inv;
#pragma unroll
        for (int d = 0; d < 16; d++) {
            sa[(lane      ) * 17 + d] += w0 * p[0][d];
            sa[(lane + 32 ) * 17 + d] += w1 * p[1][d];
            sa[(lane + 64 ) * 17 + d] += w2 * p[2][d];
        }
        if (has4) {
#pragma unroll
            for (int d = 0; d < 16; d++)
                sa[(96 + lane) * 17 + d] += w3 * p[3][d];
        }
    }
    __syncthreads();
    for (int idx = tid; idx < 1600; idx += 128) {
        int cc = idx >> 4, d = idx & 15;
        float s = sacc[0][cc * 17 + d] + sacc[1][cc * 17 + d]
                + sacc[2][cc * 17 + d] + sacc[3][cc * 17 + d];
        atomicAdd(&g_S[SOFF2 + 12800 + b * 1600 + idx], s);
    }

    __threadfence();
    __syncthreads();
    if (tid == 0) s_done = atomicAdd(&g_ctr[2], 1u);
    __syncthreads();
    if (s_done == 303u) {                            // last of 304 blocks
        __threadfence();
        for (int cap = tid; cap < 800; cap += 128)
            squash16(&g_S[SOFF2 + 12800 + cap * 16], 1.f, v2 + cap * 16);
        __syncthreads();
        for (int e = tid; e < 25600; e += 128) g_S[SOFF2 + e] = 0.f;
        if (tid == 0) g_ctr[2] = 0u;
    }
}

// ---------------------------------------------------------------------------
extern "C" void kernel_launch(void* const* d_in, const int* in_sizes, int n_in,
                              void* d_out, int out_size)
{
    const float* X  = (const float*)d_in[0];   // [8,1152,8]
    const float* W0 = (const float*)d_in[1];   // [1152,8,16,8]
    const float* W1 = (const float*)d_in[2];   // [584,20,16,16]
    const float* W2 = (const float*)d_in[3];   // [596,100,16,16]
    float* out = (float*)d_out;
    float* v0 = out;                 // [8][8][16]
    float* v1 = out + 1024;          // [8][20][16]
    float* v2 = out + 3584;          // [8][100][16]

    // ---- level 0 ----
    pred_kernel<1152, 8, 8, 4, 2, 8, 0><<<dim3(144, 1), 512>>>(
        X, W0, 1152, SOFF0, 0, nullptr);
    route0_kernel<<<dim3(19, 8), 256>>>();

    // ---- level 1 ----  (pred1 squashes S2_L0 -> vbuf, writes v0)
    pred_kernel<584, 20, 16, 2, 2, 20, 8><<<dim3(146, 1), 640>>>(
        X, W1, 576, SOFF1, SOFF0 + 1024, v0);
    route1_kernel<<<dim3(20, 8), 256>>>();

    // ---- level 2 ----  (pred2 squashes S2_L1 -> vbuf, writes v1)
    pred_kernel<596, 100, 16, 1, 4, 50, 20><<<dim3(149, 2), 800>>>(
        X, W2, 576, SOFF2, SOFF1 + 2560, v1);
    route2_kernel<<<dim3(38, 8), 128>>>(v2);
}